// round 15
// baseline (speedup 1.0000x reference)
#include <cuda_runtime.h>
#include <cuda_bf16.h>
#include <math.h>

#define B_   32
#define N_   1200
#define E_   38400
#define BN_  (B_*N_)
#define BE_  (B_*E_)
#define KS_  3      // key splits for attention
#define KC_  400    // keys per split (25 slices of 16)
#define NTILE_ (10*KS_*B_)   // 960 attention tiles

typedef unsigned long long u64;

// ---------------- f32x2 packed-math helpers ---------------------------------
__device__ __forceinline__ u64 f2fma(u64 a, u64 b, u64 c) {
    u64 d; asm("fma.rn.f32x2 %0,%1,%2,%3;" : "=l"(d) : "l"(a), "l"(b), "l"(c)); return d;
}
__device__ __forceinline__ u64 f2add(u64 a, u64 b) {
    u64 d; asm("add.rn.f32x2 %0,%1,%2;" : "=l"(d) : "l"(a), "l"(b)); return d;
}
__device__ __forceinline__ u64 f2mul(u64 a, u64 b) {
    u64 d; asm("mul.rn.f32x2 %0,%1,%2;" : "=l"(d) : "l"(a), "l"(b)); return d;
}
__device__ __forceinline__ u64 pack2(float x, float y) {
    u64 d; asm("mov.b64 %0,{%1,%2};" : "=l"(d) : "f"(x), "f"(y)); return d;
}
__device__ __forceinline__ float2 unpk(u64 v) {
    float2 r; asm("mov.b64 {%0,%1},%2;" : "=f"(r.x), "=f"(r.y) : "l"(v)); return r;
}
__device__ __forceinline__ float hadd(u64 v) { float2 r = unpk(v); return r.x + r.y; }

__device__ __forceinline__ unsigned cvt_bf16x2(float hi, float lo) {
    unsigned r; asm("cvt.rn.bf16x2.f32 %0,%1,%2;" : "=r"(r) : "f"(hi), "f"(lo)); return r;
}

__device__ __forceinline__ void mma16816(float d[4], const unsigned a[4],
                                         unsigned b0, unsigned b1) {
    asm("mma.sync.aligned.m16n8k16.row.col.f32.bf16.bf16.f32 "
        "{%0,%1,%2,%3},{%4,%5,%6,%7},{%8,%9},{%0,%1,%2,%3};"
        : "+f"(d[0]), "+f"(d[1]), "+f"(d[2]), "+f"(d[3])
        : "r"(a[0]), "r"(a[1]), "r"(a[2]), "r"(a[3]), "r"(b0), "r"(b1));
}

// q pre-scale: (1/sqrt(16)) * log2(e), so attention uses exp2
#define QSCALE 0.36067376022224085f

// ---------------- scratch (device globals) ----------------------------------
__device__ float g_xf[BN_*20];
__device__ int   g_deg[N_];
__device__ int   g_cur[N_];
__device__ int   g_off[N_+1];
__device__ int   g_srcA[E_];
__device__ float g_nrm[E_];
__device__ float g_dis[N_];
__device__ float g_pe[N_*32];
__device__ float g_h[BN_*32];
__device__ __nv_bfloat16 g_qb[(BN_+128)*32];
__device__ __nv_bfloat16 g_kb[BN_*32];
__device__ __nv_bfloat16 g_vt[BN_*32];         // per batch transposed [32 dims][1200 keys]
__device__ float g_pacc[KS_*BN_*32];
__device__ float2 g_ps[KS_*BN_];

// ---------------- merged pre: xf rows + pe table + deg zero -----------------
__global__ void k_pre(const float* __restrict__ pm, const float* __restrict__ ft) {
    int bid = blockIdx.x;
    int t = threadIdx.x;
    if (bid < 150) {
        int r = bid*256 + t;
        int b = r / N_, n = r % N_;
        float* row = &g_xf[r*20];
        row[0] = pm[(b*24 + 23)*N_ + n];
        const float* f = &ft[(((size_t)b*72 + 71)*N_ + n)*16];
#pragma unroll
        for (int c = 0; c < 16; c++) row[1+c] = f[c];
        row[17] = 0.f; row[18] = 0.f; row[19] = 0.f;
    } else if (bid < 225) {
        int id = (bid-150)*256 + t;
        int n = id >> 4, i = id & 15;
        double div = exp((double)(2*i) * (-9.210340371976184/32.0));
        double ang = (double)n * div;
        g_pe[n*32 + 2*i]   = (float)sin(ang);
        g_pe[n*32 + 2*i+1] = (float)cos(ang);
    } else {
        int i = (bid-225)*256 + t;
        if (i < N_) g_deg[i] = 0;
    }
}

__global__ void k_deg(const int* __restrict__ ei) {
    int e = blockIdx.x*blockDim.x + threadIdx.x;
    if (e < E_) atomicAdd(&g_deg[ei[BE_ + e]], 1);
}
__global__ void k_scan() {
    __shared__ int part[256];
    int t = threadIdx.x;
    int beg = t*5, end = min(beg+5, N_);
    int s = 0;
    for (int i = beg; i < end; i++) s += g_deg[i];
    part[t] = s;
    __syncthreads();
    if (t == 0) {
        int acc = 0;
        for (int i = 0; i < 256; i++) { int v = part[i]; part[i] = acc; acc += v; }
        g_off[N_] = acc;
    }
    __syncthreads();
    int acc = part[t];
    for (int i = beg; i < end; i++) {
        int d = g_deg[i];
        g_off[i] = acc; acc += d;
        g_dis[i] = d > 0 ? rsqrtf((float)d) : 0.f;
        g_cur[i] = 0;
    }
}
__global__ void k_fill(const int* __restrict__ ei) {
    int e = blockIdx.x*blockDim.x + threadIdx.x;
    if (e >= E_) return;
    int s = ei[e], d = ei[BE_ + e];
    int p = atomicAdd(&g_cur[d], 1);
    int idx = g_off[d] + p;
    g_srcA[idx] = s;
    g_nrm[idx] = -(g_dis[s] * g_dis[d]);
}

// ---------------- qkv emit (full row) ---------------------------------------
__device__ __forceinline__ void qkv_emit(const float h[32], const float* swt,
                                         const float* sbq, int r, int b, int n) {
    u64 hp[16];
#pragma unroll
    for (int u = 0; u < 16; u++) hp[u] = pack2(h[2*u], h[2*u+1]);
#pragma unroll
    for (int jb = 0; jb < 24; jb++) {
        float y[4];
#pragma unroll
        for (int uu = 0; uu < 4; uu++) {
            int j = jb*4 + uu;
            const ulonglong2* wr = (const ulonglong2*)&swt[j*32];
            u64 a0 = 0ull, a1 = 0ull;
#pragma unroll
            for (int u = 0; u < 8; u++) {
                ulonglong2 w = wr[u];
                a0 = f2fma(hp[2*u],   w.x, a0);
                a1 = f2fma(hp[2*u+1], w.y, a1);
            }
            float a = sbq[j] + hadd(f2add(a0, a1));
            if (jb < 8) a *= QSCALE;
            y[uu] = a;
        }
        int jj = (jb & 7) * 4;
        if (jb < 8) {
            uint2 p; p.x = cvt_bf16x2(y[1], y[0]); p.y = cvt_bf16x2(y[3], y[2]);
            *(uint2*)&g_qb[r*32 + jj] = p;
        } else if (jb < 16) {
            uint2 p; p.x = cvt_bf16x2(y[1], y[0]); p.y = cvt_bf16x2(y[3], y[2]);
            *(uint2*)&g_kb[r*32 + jj] = p;
        } else {
#pragma unroll
            for (int uu = 0; uu < 4; uu++) {
                int d = jj + uu;
                g_vt[((size_t)b*32 + d)*N_ + n] = __float2bfloat16_rn(y[uu]);
            }
        }
    }
}

// half version: this thread handles jb in [half*12, half*12+12); runtime half
// touches only control flow + smem offsets (register arrays stay constant-indexed)
__device__ __forceinline__ void qkv_emit_half(const float h[32], const float* swt,
                                              const float* sbq, int r, int b, int n,
                                              int half) {
    u64 hp[16];
#pragma unroll
    for (int u = 0; u < 16; u++) hp[u] = pack2(h[2*u], h[2*u+1]);
#pragma unroll
    for (int jq = 0; jq < 12; jq++) {
        int jb = half*12 + jq;
        float y[4];
#pragma unroll
        for (int uu = 0; uu < 4; uu++) {
            int j = jb*4 + uu;
            const ulonglong2* wr = (const ulonglong2*)&swt[j*32];
            u64 a0 = 0ull, a1 = 0ull;
#pragma unroll
            for (int u = 0; u < 8; u++) {
                ulonglong2 w = wr[u];
                a0 = f2fma(hp[2*u],   w.x, a0);
                a1 = f2fma(hp[2*u+1], w.y, a1);
            }
            float a = sbq[j] + hadd(f2add(a0, a1));
            if (jb < 8) a *= QSCALE;
            y[uu] = a;
        }
        int jj = (jb & 7) * 4;
        if (jb < 8) {
            uint2 p; p.x = cvt_bf16x2(y[1], y[0]); p.y = cvt_bf16x2(y[3], y[2]);
            *(uint2*)&g_qb[r*32 + jj] = p;
        } else if (jb < 16) {
            uint2 p; p.x = cvt_bf16x2(y[1], y[0]); p.y = cvt_bf16x2(y[3], y[2]);
            *(uint2*)&g_kb[r*32 + jj] = p;
        } else {
#pragma unroll
            for (int uu = 0; uu < 4; uu++) {
                int d = jj + uu;
                g_vt[((size_t)b*32 + d)*N_ + n] = __float2bfloat16_rn(y[uu]);
            }
        }
    }
}

// ---------------- GCN + input proj + pos-enc + QKV(l0) ----------------------
__global__ void __launch_bounds__(128) k_gcn_qkv(
                      const float* __restrict__ w0, const float* __restrict__ w1,
                      const float* __restrict__ bch, const float* __restrict__ win,
                      const float* __restrict__ bin,
                      const float* __restrict__ wq, const float* __restrict__ bq) {
    __shared__ float sw0[17*14], sw1[17*14], sbch[14], swint[32*32], sbin[32];
    __shared__ float swt[96*32], sbq[96];
    int t = threadIdx.x;
    for (int i = t; i < 17*14; i += 128) { sw0[i] = w0[i]; sw1[i] = w1[i]; }
    for (int i = t; i < 14; i += 128) sbch[i] = bch[i];
    for (int i = t; i < 32*32; i += 128) {
        int j = i >> 5, ii = i & 31;
        swint[i] = (ii < 31) ? win[ii*32 + j] : 0.f;
    }
    for (int i = t; i < 32; i += 128) sbin[i] = bin[i];
    for (int i = t; i < 96*32; i += 128) {
        int j = i >> 5, ii = i & 31;
        swt[i] = wq[ii*96 + j];
    }
    for (int i = t; i < 96; i += 128) sbq[i] = bq[i];
    __syncthreads();

    int r = blockIdx.x*128 + t;
    int b = r / N_, n = r % N_;

    u64 xgp[10], txp[10];
    const ulonglong2* xr = (const ulonglong2*)&g_xf[r*20];
#pragma unroll
    for (int u = 0; u < 5; u++) {
        ulonglong2 v = xr[u];
        xgp[2*u] = v.x; xgp[2*u+1] = v.y;
        txp[2*u] = 0ull; txp[2*u+1] = 0ull;
    }
    int beg = g_off[n], end = g_off[n+1];
    int base = b * N_;
    for (int kk = beg; kk < end; kk++) {
        int sN = g_srcA[kk];
        u64 wp = pack2(g_nrm[kk], g_nrm[kk]);
        const ulonglong2* sr = (const ulonglong2*)&g_xf[(base + sN)*20];
#pragma unroll
        for (int u = 0; u < 5; u++) {
            ulonglong2 v = sr[u];
            txp[2*u]   = f2fma(wp, v.x, txp[2*u]);
            txp[2*u+1] = f2fma(wp, v.y, txp[2*u+1]);
        }
    }
    float xg[20], tx[20];
#pragma unroll
    for (int u = 0; u < 10; u++) {
        float2 a = unpk(xgp[u]); xg[2*u] = a.x; xg[2*u+1] = a.y;
        float2 c = unpk(txp[u]); tx[2*u] = c.x; tx[2*u+1] = c.y;
    }
    float xv[32];
#pragma unroll
    for (int i = 0; i < 17; i++) xv[i] = xg[i];
#pragma unroll
    for (int j = 0; j < 14; j++) {
        float a = sbch[j];
#pragma unroll
        for (int i = 0; i < 17; i++) a += xg[i]*sw0[i*14+j] + tx[i]*sw1[i*14+j];
        xv[17+j] = 1.f / (1.f + __expf(-a));
    }
    xv[31] = 0.f;
    u64 xvp[16];
#pragma unroll
    for (int u = 0; u < 16; u++) xvp[u] = pack2(xv[2*u], xv[2*u+1]);

    const float2* pe = (const float2*)&g_pe[n*32];
    float h[32];
#pragma unroll
    for (int j = 0; j < 32; j++) {
        const ulonglong2* wr = (const ulonglong2*)&swint[j*32];
        u64 a0 = 0ull, a1 = 0ull;
#pragma unroll
        for (int u = 0; u < 8; u++) {
            ulonglong2 w = wr[u];
            a0 = f2fma(xvp[2*u],   w.x, a0);
            a1 = f2fma(xvp[2*u+1], w.y, a1);
        }
        h[j] = sbin[j] + hadd(f2add(a0, a1));
    }
#pragma unroll
    for (int u = 0; u < 16; u++) {
        float2 p = pe[u];
        h[2*u] += p.x; h[2*u+1] += p.y;
    }
    float4* hw = (float4*)&g_h[r*32];
#pragma unroll
    for (int u = 0; u < 8; u++)
        hw[u] = make_float4(h[4*u], h[4*u+1], h[4*u+2], h[4*u+3]);

    qkv_emit(h, swt, sbq, r, b, n);
}

// ---------------- tensor-core attention partial (split-K; R9 form) ----------
__global__ void __launch_bounds__(128, 4) k_attn_tc() {
    int tid = threadIdx.x;
    int lane = tid & 31, warp = tid >> 5;
    int gq = lane >> 2, qu = lane & 3;

#pragma unroll 1
    for (int it = 0; it < 2; it++) {
        int tile = blockIdx.x*2 + it;
        int qt = tile % 10;
        int ks = (tile/10) % KS_;
        int b  = tile / (10*KS_);
        int wq0 = qt*128 + warp*32;

        unsigned aQ[2][2][4];
        {
            const __nv_bfloat16* qbase = &g_qb[((size_t)b*N_ + wq0)*32];
#pragma unroll
            for (int h = 0; h < 2; h++)
#pragma unroll
                for (int m = 0; m < 2; m++) {
                    const __nv_bfloat16* p0 = qbase + (16*m + gq)*32 + 16*h + 2*qu;
                    aQ[h][m][0] = *(const unsigned*)(p0);
                    aQ[h][m][1] = *(const unsigned*)(p0 + 8*32);
                    aQ[h][m][2] = *(const unsigned*)(p0 + 8);
                    aQ[h][m][3] = *(const unsigned*)(p0 + 8*32 + 8);
                }
        }

        float O[2][2][2][4];
        float ssum[2][2][2];
#pragma unroll
        for (int h = 0; h < 2; h++)
#pragma unroll
            for (int m = 0; m < 2; m++) {
#pragma unroll
                for (int nd = 0; nd < 2; nd++)
#pragma unroll
                    for (int x = 0; x < 4; x++) O[h][m][nd][x] = 0.f;
                ssum[h][m][0] = 0.f; ssum[h][m][1] = 0.f;
            }

        const __nv_bfloat16* kbase = &g_kb[(size_t)b*N_*32];
        const __nv_bfloat16* vbase = &g_vt[(size_t)b*32*N_];

        int k0 = ks*KC_;
#pragma unroll 1
        for (int sl = 0; sl < KC_/16; sl++, k0 += 16) {
            unsigned kb0[2][2], kb1[2][2], vb0[2][2], vb1[2][2];
#pragma unroll
            for (int h = 0; h < 2; h++)
#pragma unroll
                for (int nb = 0; nb < 2; nb++) {
                    const __nv_bfloat16* kp = kbase + (k0 + 8*nb + gq)*32 + 16*h + 2*qu;
                    kb0[h][nb] = *(const unsigned*)(kp);
                    kb1[h][nb] = *(const unsigned*)(kp + 8);
                }
#pragma unroll
            for (int h = 0; h < 2; h++)
#pragma unroll
                for (int nd = 0; nd < 2; nd++) {
                    const __nv_bfloat16* vp = vbase + (size_t)(16*h + 8*nd + gq)*N_ + k0 + 2*qu;
                    vb0[h][nd] = *(const unsigned*)(vp);
                    vb1[h][nd] = *(const unsigned*)(vp + 8);
                }

            float S[2][2][2][4];
#pragma unroll
            for (int h = 0; h < 2; h++)
#pragma unroll
                for (int nb = 0; nb < 2; nb++)
#pragma unroll
                    for (int m = 0; m < 2; m++) {
#pragma unroll
                        for (int x = 0; x < 4; x++) S[h][m][nb][x] = 0.f;
                        mma16816(S[h][m][nb], aQ[h][m], kb0[h][nb], kb1[h][nb]);
                    }

            unsigned aP[2][2][4];
#pragma unroll
            for (int h = 0; h < 2; h++)
#pragma unroll
                for (int m = 0; m < 2; m++)
#pragma unroll
                    for (int nb = 0; nb < 2; nb++) {
                        float e0 = exp2f(S[h][m][nb][0]);
                        float e1 = exp2f(S[h][m][nb][1]);
                        float e2 = exp2f(S[h][m][nb][2]);
                        float e3 = exp2f(S[h][m][nb][3]);
                        ssum[h][m][0] += e0 + e1;
                        ssum[h][m][1] += e2 + e3;
                        aP[h][m][2*nb]   = cvt_bf16x2(e1, e0);
                        aP[h][m][2*nb+1] = cvt_bf16x2(e3, e2);
                    }

#pragma unroll
            for (int h = 0; h < 2; h++)
#pragma unroll
                for (int nd = 0; nd < 2; nd++)
#pragma unroll
                    for (int m = 0; m < 2; m++)
                        mma16816(O[h][m][nd], aP[h][m], vb0[h][nd], vb1[h][nd]);
        }

#pragma unroll
        for (int h = 0; h < 2; h++)
#pragma unroll
            for (int m = 0; m < 2; m++)
#pragma unroll
                for (int x = 0; x < 2; x++) {
                    float v = ssum[h][m][x];
                    v += __shfl_xor_sync(0xffffffffu, v, 1);
                    v += __shfl_xor_sync(0xffffffffu, v, 2);
                    ssum[h][m][x] = v;
                }

        size_t pbase = (size_t)ks*BN_ + (size_t)b*N_;
#pragma unroll
        for (int m = 0; m < 2; m++) {
            int r0 = wq0 + 16*m + gq;
            if (r0 < N_) {
                float* dst = &g_pacc[(pbase + r0)*32];
#pragma unroll
                for (int h = 0; h < 2; h++)
#pragma unroll
                    for (int nd = 0; nd < 2; nd++)
                        *(float2*)&dst[16*h + 8*nd + 2*qu] =
                            make_float2(O[h][m][nd][0], O[h][m][nd][1]);
                if (qu == 0)
                    g_ps[pbase + r0] = make_float2(ssum[0][m][0], ssum[1][m][0]);
            }
            int r1 = r0 + 8;
            if (r1 < N_) {
                float* dst = &g_pacc[(pbase + r1)*32];
#pragma unroll
                for (int h = 0; h < 2; h++)
#pragma unroll
                    for (int nd = 0; nd < 2; nd++)
                        *(float2*)&dst[16*h + 8*nd + 2*qu] =
                            make_float2(O[h][m][nd][2], O[h][m][nd][3]);
                if (qu == 0)
                    g_ps[pbase + r1] = make_float2(ssum[0][m][1], ssum[1][m][1]);
            }
        }
    }
}

// ---- warp-split combine + Wo + LN1 + FFN + LN2 (2 threads/row, smem xchg) --
// 64 rows/block, 128 threads: warps 0-1 = half 0, warps 2-3 = half 1 (uniform).
// All register arrays constant-indexed; half affects only smem offsets/ranges.
// hout[] is valid only for half==0 threads on return.
__device__ __forceinline__ void comb_ff_ws(
        const float* swot, const float* sbo, const float* sg1, const float* sb1ln,
        const float* sw1t, const float* sw2, const float* sbf1,
        const float* sbf2, const float* sg2, const float* sbn,
        float* sx, float* sred,
        int r, int row, int half, float hout[32]) {
    // ---- combine split-K partials (full; duplicated across halves) ----
    u64 accp[16];
    float s0 = 0.f, s1 = 0.f;
#pragma unroll
    for (int ks = 0; ks < KS_; ks++) {
        const ulonglong2* pa = (const ulonglong2*)&g_pacc[((size_t)ks*BN_ + r)*32];
#pragma unroll
        for (int u = 0; u < 8; u++) {
            ulonglong2 v = pa[u];
            if (ks == 0) { accp[2*u] = v.x; accp[2*u+1] = v.y; }
            else { accp[2*u] = f2add(accp[2*u], v.x); accp[2*u+1] = f2add(accp[2*u+1], v.y); }
        }
        float2 s = g_ps[ks*BN_ + r];
        s0 += s.x; s1 += s.y;
    }
    float i0 = 1.f/s0, i1 = 1.f/s1;
    u64 i0p = pack2(i0, i0), i1p = pack2(i1, i1);
    u64 op[16];
#pragma unroll
    for (int u = 0; u < 8; u++) { op[u] = f2mul(accp[u], i0p); op[8+u] = f2mul(accp[8+u], i1p); }

    int jb16 = half*16;
    // residual h for this half: 16 contiguous floats at runtime base (constant regs)
    float hold[16];
    {
        const float4* hf = (const float4*)&g_h[r*32 + jb16];
#pragma unroll
        for (int u = 0; u < 4; u++) {
            float4 v = hf[u];
            hold[4*u]=v.x; hold[4*u+1]=v.y; hold[4*u+2]=v.z; hold[4*u+3]=v.w;
        }
    }
    // ---- z half: 16 Wo columns ----
    float zh[16];
#pragma unroll
    for (int jj = 0; jj < 16; jj++) {
        int j = jb16 + jj;
        const ulonglong2* wr = (const ulonglong2*)&swot[j*32];
        u64 a0 = 0ull, a1 = 0ull;
#pragma unroll
        for (int u = 0; u < 8; u++) {
            ulonglong2 w = wr[u];
            a0 = f2fma(op[2*u],   w.x, a0);
            a1 = f2fma(op[2*u+1], w.y, a1);
        }
        zh[jj] = sbo[j] + hold[jj] + hadd(f2add(a0, a1));
    }
    // ---- LN1 cross-half reduction via sred (A=sum at [0..127], B=var at [128..255])
    float lsum = 0.f;
#pragma unroll
    for (int jj = 0; jj < 16; jj++) lsum += zh[jj];
    sred[half*64 + row] = lsum;
    __syncthreads();
    float mu = (sred[row] + sred[64 + row]) * (1.f/32.f);
    float lvar = 0.f;
#pragma unroll
    for (int jj = 0; jj < 16; jj++) { float d = zh[jj]-mu; lvar += d*d; }
    sred[128 + half*64 + row] = lvar;
    __syncthreads();
    float var = (sred[128 + row] + sred[192 + row]) * (1.f/32.f);
    float inv = rsqrtf(var + 1e-5f);
    // ---- write h1 half to sx; read back full ----
#pragma unroll
    for (int jj = 0; jj < 16; jj++) {
        int j = jb16 + jj;
        sx[row*32 + j] = (zh[jj]-mu)*inv*sg1[j] + sb1ln[j];
    }
    __syncthreads();
    float h1[32];
#pragma unroll
    for (int j = 0; j < 32; j++) h1[j] = sx[row*32 + j];

    // ---- FFN: this half handles 64 of 128 hidden units ----
    u64 hp[16], yp[16];
#pragma unroll
    for (int u = 0; u < 16; u++) {
        hp[u] = pack2(h1[2*u], h1[2*u+1]);
        yp[u] = (half == 0) ? pack2(h1[2*u] + sbf2[2*u], h1[2*u+1] + sbf2[2*u+1]) : 0ull;
    }
    int hbase = half*64;
#pragma unroll 4
    for (int jq = 0; jq < 64; jq++) {
        int j = hbase + jq;
        const ulonglong2* wr = (const ulonglong2*)&sw1t[j*32];
        u64 a0 = 0ull, a1 = 0ull;
#pragma unroll
        for (int u = 0; u < 8; u++) {
            ulonglong2 w = wr[u];
            a0 = f2fma(hp[2*u],   w.x, a0);
            a1 = f2fma(hp[2*u+1], w.y, a1);
        }
        float uact = fmaxf(sbf1[j] + hadd(f2add(a0, a1)), 0.f);
        u64 up = pack2(uact, uact);
        const ulonglong2* w2r = (const ulonglong2*)&sw2[j*32];
#pragma unroll
        for (int u = 0; u < 8; u++) {
            ulonglong2 w = w2r[u];
            yp[2*u]   = f2fma(up, w.x, yp[2*u]);
            yp[2*u+1] = f2fma(up, w.y, yp[2*u+1]);
        }
    }
    // ---- y reduction: half1 -> sx, half0 adds, LN2 (half0 only) ----
    __syncthreads();   // all h1 reads of sx complete
    if (half == 1) {
#pragma unroll
        for (int u = 0; u < 16; u++) {
            float2 v = unpk(yp[u]);
            sx[row*32 + 2*u] = v.x; sx[row*32 + 2*u+1] = v.y;
        }
    }
    __syncthreads();
    if (half == 0) {
        float y[32];
#pragma unroll
        for (int u = 0; u < 16; u++) {
            float2 v = unpk(yp[u]);
            y[2*u]   = v.x + sx[row*32 + 2*u];
            y[2*u+1] = v.y + sx[row*32 + 2*u+1];
        }
        float mu2 = 0.f;
#pragma unroll
        for (int j = 0; j < 32; j++) mu2 += y[j];
        mu2 *= (1.f/32.f);
        float var2 = 0.f;
#pragma unroll
        for (int j = 0; j < 32; j++) { float d = y[j]-mu2; var2 += d*d; }
        var2 *= (1.f/32.f);
        float inv2 = rsqrtf(var2 + 1e-5f);
#pragma unroll
        for (int j = 0; j < 32; j++) hout[j] = (y[j]-mu2)*inv2*sg2[j] + sbn[j];
    }
}

// ---- layer-0 epilogue: comb+ff (warp-split), write h, emit layer-1 QKV -----
__global__ void __launch_bounds__(128) k_comb_ff_qkv(
        const float* __restrict__ wo, const float* __restrict__ bo,
        const float* __restrict__ g1, const float* __restrict__ b1,
        const float* __restrict__ w1, const float* __restrict__ bb1,
        const float* __restrict__ w2, const float* __restrict__ bb2,
        const float* __restrict__ g2, const float* __restrict__ b2ln,
        const float* __restrict__ wq, const float* __restrict__ bq) {
    __shared__ float swot[1024], sw1t[4096], sw2[4096];
    __shared__ float sx[64*32], sred[256];
    __shared__ float sbo[32], sg1[32], sb1ln[32], sbf1[128], sbf2[32], sg2[32], sbn[32];
    __shared__ float sbq[96];
    int t = threadIdx.x;
    for (int i = t; i < 1024; i += 128) {
        int j = i >> 5, ii = i & 31;
        swot[i] = wo[ii*32 + j];
    }
    for (int i = t; i < 4096; i += 128) {
        int j = i >> 5, ii = i & 31;   // sw1t[j*32+ii] = w1[ii*128+j]
        sw1t[i] = w1[ii*128 + j];
        sw2[i]  = w2[i];
    }
    if (t < 32) {
        sbo[t] = bo[t]; sg1[t] = g1[t]; sb1ln[t] = b1[t];
        sbf2[t] = bb2[t]; sg2[t] = g2[t]; sbn[t] = b2ln[t];
    }
    for (int i = t; i < 128; i += 128) sbf1[i] = bb1[i];
    for (int i = t; i < 96; i += 128) sbq[i] = bq[i];
    __syncthreads();

    int row = t & 63, half = t >> 6;
    int r = blockIdx.x*64 + row;
    int b = r / N_, n = r % N_;
    float hnew[32];
    comb_ff_ws(swot, sbo, sg1, sb1ln, sw1t, sw2, sbf1, sbf2, sg2, sbn,
               sx, sred, r, row, half, hnew);
    if (half == 0) {
        float4* hw = (float4*)&g_h[r*32];
#pragma unroll
        for (int u = 0; u < 8; u++)
            hw[u] = make_float4(hnew[4*u], hnew[4*u+1], hnew[4*u+2], hnew[4*u+3]);
#pragma unroll
        for (int j = 0; j < 32; j++) sx[row*32 + j] = hnew[j];
    }
    __syncthreads();
    float hn[32];
#pragma unroll
    for (int j = 0; j < 32; j++) hn[j] = (half == 0) ? hnew[j] : sx[row*32 + j];
    // reuse sw1t for layer-1 QKV weights (FFN reads complete)
    for (int i = t; i < 96*32; i += 128) {
        int j = i >> 5, ii = i & 31;
        sw1t[i] = wq[ii*96 + j];
    }
    __syncthreads();
    qkv_emit_half(hn, sw1t, sbq, r, b, n, half);
}

__global__ void __launch_bounds__(128) k_comb_ff_out(
        const float* __restrict__ wo, const float* __restrict__ bo,
        const float* __restrict__ g1, const float* __restrict__ b1,
        const float* __restrict__ w1, const float* __restrict__ bb1,
        const float* __restrict__ w2, const float* __restrict__ bb2,
        const float* __restrict__ g2, const float* __restrict__ b2ln,
        const float* __restrict__ wout, const float* __restrict__ bout,
        float* __restrict__ out) {
    __shared__ float swot[1024], sw1t[4096], sw2[4096];
    __shared__ float sx[64*32], sred[256];
    __shared__ float sbo[32], sg1[32], sb1ln[32], sbf1[128], sbf2[32], sg2[32], sbn[32];
    __shared__ float swo2[32];
    __shared__ float sb0;
    int t = threadIdx.x;
    for (int i = t; i < 1024; i += 128) {
        int j = i >> 5, ii = i & 31;
        swot[i] = wo[ii*32 + j];
    }
    for (int i = t; i < 4096; i += 128) {
        int j = i >> 5, ii = i & 31;
        sw1t[i] = w1[ii*128 + j];
        sw2[i]  = w2[i];
    }
    if (t < 32) {
        sbo[t] = bo[t]; sg1[t] = g1[t]; sb1ln[t] = b1[t];
        sbf2[t] = bb2[t]; sg2[t] = g2[t]; sbn[t] = b2ln[t];
        swo2[t] = wout[t];
    }
    if (t == 0) sb0 = bout[0];
    for (int i = t; i < 128; i += 128) sbf1[i] = bb1[i];
    __syncthreads();

    int row = t & 63, half = t >> 6;
    int r = blockIdx.x*64 + row;
    float hnew[32];
    comb_ff_ws(swot, sbo, sg1, sb1ln, sw1t, sw2, sbf1, sbf2, sg2, sbn,
               sx, sred, r, row, half, hnew);
    if (half == 0) {
        float a = sb0;
#pragma unroll
        for (int j = 0; j < 32; j++) a += hnew[j]*swo2[j];
        out[r] = a;
    }
}

// ---------------- launch -----------------------------------------------------
extern "C" void kernel_launch(void* const* d_in, const int* in_sizes, int n_in,
                              void* d_out, int out_size) {
    const float* pm    = (const float*)d_in[0];
    const float* ft    = (const float*)d_in[1];
    const int*   ei    = (const int*)  d_in[2];
    const float* wch0  = (const float*)d_in[3];
    const float* wch1  = (const float*)d_in[4];
    const float* bch   = (const float*)d_in[5];
    const float* win   = (const float*)d_in[6];
    const float* bin   = (const float*)d_in[7];
    const float* wqkv  = (const float*)d_in[8];
    const float* bqkv  = (const float*)d_in[9];
    const float* wo    = (const float*)d_in[10];
    const float* bo    = (const float*)d_in[11];
    const float* ln1g  = (const float*)d_in[12];
    const float* ln1b  = (const float*)d_in[13];
    const float* wff1  = (const float*)d_in[14];
    const float* bff1  = (const float*)d_in[15];
    const float* wff2  = (const float*)d_in[16];
    const float* bff2  = (const float*)d_in[17];
    const float* ln2g  = (const float*)d_in[18];
    const float* ln2b  = (const float*)d_in[19];
    const float* wout  = (const float*)d_in[20];
    const float* bout  = (const float*)d_in[21];
    float* out = (float*)d_out;

    k_pre <<<230, 256>>>(pm, ft);
    k_deg <<<(E_+255)/256, 256>>>(ei);
    k_scan<<<1, 256>>>();
    k_fill<<<(E_+255)/256, 256>>>(ei);
    k_gcn_qkv<<<BN_/128, 128>>>(wch0, wch1, bch, win, bin, wqkv, bqkv);

    k_attn_tc<<<NTILE_/2, 128>>>();
    k_comb_ff_qkv<<<BN_/64, 128>>>(wo, bo, ln1g, ln1b,
                                   wff1, bff1, wff2, bff2, ln2g, ln2b,
                                   wqkv + 32*96, bqkv + 96);
    k_attn_tc<<<NTILE_/2, 128>>>();
    k_comb_ff_out<<<BN_/64, 128>>>(wo + 1024, bo + 32, ln1g + 32, ln1b + 32,
                                   wff1 + 32*128, bff1 + 128,
                                   wff2 + 128*32, bff2 + 32,
                                   ln2g + 32, ln2b + 32,
                                   wout, bout, out);
}

// round 16
// speedup vs baseline: 1.1417x; 1.1417x over previous
#include <cuda_runtime.h>
#include <cuda_bf16.h>
#include <math.h>

#define B_   32
#define N_   1200
#define E_   38400
#define BN_  (B_*N_)
#define BE_  (B_*E_)
#define KS_  3      // key splits for attention
#define KC_  400    // keys per split (25 slices of 16)
#define NTILE_ (10*KS_*B_)   // 960 attention tiles
#define AGRID_ 592           // 148 SMs * 4 blocks; balanced contiguous partition

typedef unsigned long long u64;

// ---------------- f32x2 packed-math helpers ---------------------------------
__device__ __forceinline__ u64 f2fma(u64 a, u64 b, u64 c) {
    u64 d; asm("fma.rn.f32x2 %0,%1,%2,%3;" : "=l"(d) : "l"(a), "l"(b), "l"(c)); return d;
}
__device__ __forceinline__ u64 f2add(u64 a, u64 b) {
    u64 d; asm("add.rn.f32x2 %0,%1,%2;" : "=l"(d) : "l"(a), "l"(b)); return d;
}
__device__ __forceinline__ u64 f2mul(u64 a, u64 b) {
    u64 d; asm("mul.rn.f32x2 %0,%1,%2;" : "=l"(d) : "l"(a), "l"(b)); return d;
}
__device__ __forceinline__ u64 pack2(float x, float y) {
    u64 d; asm("mov.b64 %0,{%1,%2};" : "=l"(d) : "f"(x), "f"(y)); return d;
}
__device__ __forceinline__ float2 unpk(u64 v) {
    float2 r; asm("mov.b64 {%0,%1},%2;" : "=f"(r.x), "=f"(r.y) : "l"(v)); return r;
}
__device__ __forceinline__ float hadd(u64 v) { float2 r = unpk(v); return r.x + r.y; }

__device__ __forceinline__ unsigned cvt_bf16x2(float hi, float lo) {
    unsigned r; asm("cvt.rn.bf16x2.f32 %0,%1,%2;" : "=r"(r) : "f"(hi), "f"(lo)); return r;
}

__device__ __forceinline__ void mma16816(float d[4], const unsigned a[4],
                                         unsigned b0, unsigned b1) {
    asm("mma.sync.aligned.m16n8k16.row.col.f32.bf16.bf16.f32 "
        "{%0,%1,%2,%3},{%4,%5,%6,%7},{%8,%9},{%0,%1,%2,%3};"
        : "+f"(d[0]), "+f"(d[1]), "+f"(d[2]), "+f"(d[3])
        : "r"(a[0]), "r"(a[1]), "r"(a[2]), "r"(a[3]), "r"(b0), "r"(b1));
}

// q pre-scale: (1/sqrt(16)) * log2(e), so attention uses exp2
#define QSCALE 0.36067376022224085f

// ---------------- scratch (device globals) ----------------------------------
__device__ float g_xf[BN_*20];
__device__ int   g_deg[N_];
__device__ int   g_cur[N_];
__device__ int   g_off[N_+1];
__device__ int   g_srcA[E_];
__device__ float g_nrm[E_];
__device__ float g_dis[N_];
__device__ float g_pe[N_*32];
__device__ float g_h[BN_*32];
__device__ __nv_bfloat16 g_qb[(BN_+128)*32];
__device__ __nv_bfloat16 g_kb[BN_*32];
__device__ __nv_bfloat16 g_vt[BN_*32];         // per batch transposed [32 dims][1200 keys]
__device__ float g_pacc[KS_*BN_*32];
__device__ float2 g_ps[KS_*BN_];

// ---------------- merged pre: xf rows + pe table + deg zero -----------------
__global__ void k_pre(const float* __restrict__ pm, const float* __restrict__ ft) {
    int bid = blockIdx.x;
    int t = threadIdx.x;
    if (bid < 150) {
        int r = bid*256 + t;
        int b = r / N_, n = r % N_;
        float* row = &g_xf[r*20];
        row[0] = pm[(b*24 + 23)*N_ + n];
        const float* f = &ft[(((size_t)b*72 + 71)*N_ + n)*16];
#pragma unroll
        for (int c = 0; c < 16; c++) row[1+c] = f[c];
        row[17] = 0.f; row[18] = 0.f; row[19] = 0.f;
    } else if (bid < 225) {
        int id = (bid-150)*256 + t;
        int n = id >> 4, i = id & 15;
        double div = exp((double)(2*i) * (-9.210340371976184/32.0));
        double ang = (double)n * div;
        g_pe[n*32 + 2*i]   = (float)sin(ang);
        g_pe[n*32 + 2*i+1] = (float)cos(ang);
    } else {
        int i = (bid-225)*256 + t;
        if (i < N_) g_deg[i] = 0;
    }
}

__global__ void k_deg(const int* __restrict__ ei) {
    int e = blockIdx.x*blockDim.x + threadIdx.x;
    if (e < E_) atomicAdd(&g_deg[ei[BE_ + e]], 1);
}
__global__ void k_scan() {
    __shared__ int part[256];
    int t = threadIdx.x;
    int beg = t*5, end = min(beg+5, N_);
    int s = 0;
    for (int i = beg; i < end; i++) s += g_deg[i];
    part[t] = s;
    __syncthreads();
    if (t == 0) {
        int acc = 0;
        for (int i = 0; i < 256; i++) { int v = part[i]; part[i] = acc; acc += v; }
        g_off[N_] = acc;
    }
    __syncthreads();
    int acc = part[t];
    for (int i = beg; i < end; i++) {
        int d = g_deg[i];
        g_off[i] = acc; acc += d;
        g_dis[i] = d > 0 ? rsqrtf((float)d) : 0.f;
        g_cur[i] = 0;
    }
}
__global__ void k_fill(const int* __restrict__ ei) {
    int e = blockIdx.x*blockDim.x + threadIdx.x;
    if (e >= E_) return;
    int s = ei[e], d = ei[BE_ + e];
    int p = atomicAdd(&g_cur[d], 1);
    int idx = g_off[d] + p;
    g_srcA[idx] = s;
    g_nrm[idx] = -(g_dis[s] * g_dis[d]);
}

// ---------------- qkv emit (full row) ---------------------------------------
__device__ __forceinline__ void qkv_emit(const float h[32], const float* swt,
                                         const float* sbq, int r, int b, int n) {
    u64 hp[16];
#pragma unroll
    for (int u = 0; u < 16; u++) hp[u] = pack2(h[2*u], h[2*u+1]);
#pragma unroll
    for (int jb = 0; jb < 24; jb++) {
        float y[4];
#pragma unroll
        for (int uu = 0; uu < 4; uu++) {
            int j = jb*4 + uu;
            const ulonglong2* wr = (const ulonglong2*)&swt[j*32];
            u64 a0 = 0ull, a1 = 0ull;
#pragma unroll
            for (int u = 0; u < 8; u++) {
                ulonglong2 w = wr[u];
                a0 = f2fma(hp[2*u],   w.x, a0);
                a1 = f2fma(hp[2*u+1], w.y, a1);
            }
            float a = sbq[j] + hadd(f2add(a0, a1));
            if (jb < 8) a *= QSCALE;
            y[uu] = a;
        }
        int jj = (jb & 7) * 4;
        if (jb < 8) {
            uint2 p; p.x = cvt_bf16x2(y[1], y[0]); p.y = cvt_bf16x2(y[3], y[2]);
            *(uint2*)&g_qb[r*32 + jj] = p;
        } else if (jb < 16) {
            uint2 p; p.x = cvt_bf16x2(y[1], y[0]); p.y = cvt_bf16x2(y[3], y[2]);
            *(uint2*)&g_kb[r*32 + jj] = p;
        } else {
#pragma unroll
            for (int uu = 0; uu < 4; uu++) {
                int d = jj + uu;
                g_vt[((size_t)b*32 + d)*N_ + n] = __float2bfloat16_rn(y[uu]);
            }
        }
    }
}

// ---------------- GCN + input proj + pos-enc + QKV(l0) ----------------------
__global__ void __launch_bounds__(128) k_gcn_qkv(
                      const float* __restrict__ w0, const float* __restrict__ w1,
                      const float* __restrict__ bch, const float* __restrict__ win,
                      const float* __restrict__ bin,
                      const float* __restrict__ wq, const float* __restrict__ bq) {
    __shared__ float sw0[17*14], sw1[17*14], sbch[14], swint[32*32], sbin[32];
    __shared__ float swt[96*32], sbq[96];
    int t = threadIdx.x;
    for (int i = t; i < 17*14; i += 128) { sw0[i] = w0[i]; sw1[i] = w1[i]; }
    for (int i = t; i < 14; i += 128) sbch[i] = bch[i];
    for (int i = t; i < 32*32; i += 128) {
        int j = i >> 5, ii = i & 31;
        swint[i] = (ii < 31) ? win[ii*32 + j] : 0.f;
    }
    for (int i = t; i < 32; i += 128) sbin[i] = bin[i];
    for (int i = t; i < 96*32; i += 128) {
        int j = i >> 5, ii = i & 31;
        swt[i] = wq[ii*96 + j];
    }
    for (int i = t; i < 96; i += 128) sbq[i] = bq[i];
    __syncthreads();

    int r = blockIdx.x*128 + t;
    int b = r / N_, n = r % N_;

    u64 xgp[10], txp[10];
    const ulonglong2* xr = (const ulonglong2*)&g_xf[r*20];
#pragma unroll
    for (int u = 0; u < 5; u++) {
        ulonglong2 v = xr[u];
        xgp[2*u] = v.x; xgp[2*u+1] = v.y;
        txp[2*u] = 0ull; txp[2*u+1] = 0ull;
    }
    int beg = g_off[n], end = g_off[n+1];
    int base = b * N_;
    for (int kk = beg; kk < end; kk++) {
        int sN = g_srcA[kk];
        u64 wp = pack2(g_nrm[kk], g_nrm[kk]);
        const ulonglong2* sr = (const ulonglong2*)&g_xf[(base + sN)*20];
#pragma unroll
        for (int u = 0; u < 5; u++) {
            ulonglong2 v = sr[u];
            txp[2*u]   = f2fma(wp, v.x, txp[2*u]);
            txp[2*u+1] = f2fma(wp, v.y, txp[2*u+1]);
        }
    }
    float xg[20], tx[20];
#pragma unroll
    for (int u = 0; u < 10; u++) {
        float2 a = unpk(xgp[u]); xg[2*u] = a.x; xg[2*u+1] = a.y;
        float2 c = unpk(txp[u]); tx[2*u] = c.x; tx[2*u+1] = c.y;
    }
    float xv[32];
#pragma unroll
    for (int i = 0; i < 17; i++) xv[i] = xg[i];
#pragma unroll
    for (int j = 0; j < 14; j++) {
        float a = sbch[j];
#pragma unroll
        for (int i = 0; i < 17; i++) a += xg[i]*sw0[i*14+j] + tx[i]*sw1[i*14+j];
        xv[17+j] = 1.f / (1.f + __expf(-a));
    }
    xv[31] = 0.f;
    u64 xvp[16];
#pragma unroll
    for (int u = 0; u < 16; u++) xvp[u] = pack2(xv[2*u], xv[2*u+1]);

    const float2* pe = (const float2*)&g_pe[n*32];
    float h[32];
#pragma unroll
    for (int j = 0; j < 32; j++) {
        const ulonglong2* wr = (const ulonglong2*)&swint[j*32];
        u64 a0 = 0ull, a1 = 0ull;
#pragma unroll
        for (int u = 0; u < 8; u++) {
            ulonglong2 w = wr[u];
            a0 = f2fma(xvp[2*u],   w.x, a0);
            a1 = f2fma(xvp[2*u+1], w.y, a1);
        }
        h[j] = sbin[j] + hadd(f2add(a0, a1));
    }
#pragma unroll
    for (int u = 0; u < 16; u++) {
        float2 p = pe[u];
        h[2*u] += p.x; h[2*u+1] += p.y;
    }
    float4* hw = (float4*)&g_h[r*32];
#pragma unroll
    for (int u = 0; u < 8; u++)
        hw[u] = make_float4(h[4*u], h[4*u+1], h[4*u+2], h[4*u+3]);

    qkv_emit(h, swt, sbq, r, b, n);
}

// ---------------- tensor-core attention partial (split-K) -------------------
// 592 blocks (=148*4, one wave), balanced contiguous tile partition:
// block i handles tiles [i*960/592, (i+1)*960/592) -> 1 or 2 consecutive
// tiles; per-SM totals 6 or 7 (tail 1.08 vs 1.23 at 480x2).
__global__ void __launch_bounds__(128, 4) k_attn_tc() {
    int tid = threadIdx.x;
    int lane = tid & 31, warp = tid >> 5;
    int gq = lane >> 2, qu = lane & 3;
    int t0 = (int)(((long long)blockIdx.x     * NTILE_) / AGRID_);
    int t1 = (int)(((long long)(blockIdx.x+1) * NTILE_) / AGRID_);

#pragma unroll 1
    for (int tile = t0; tile < t1; tile++) {
        int qt = tile % 10;
        int ks = (tile/10) % KS_;
        int b  = tile / (10*KS_);
        int wq0 = qt*128 + warp*32;

        unsigned aQ[2][2][4];
        {
            const __nv_bfloat16* qbase = &g_qb[((size_t)b*N_ + wq0)*32];
#pragma unroll
            for (int h = 0; h < 2; h++)
#pragma unroll
                for (int m = 0; m < 2; m++) {
                    const __nv_bfloat16* p0 = qbase + (16*m + gq)*32 + 16*h + 2*qu;
                    aQ[h][m][0] = *(const unsigned*)(p0);
                    aQ[h][m][1] = *(const unsigned*)(p0 + 8*32);
                    aQ[h][m][2] = *(const unsigned*)(p0 + 8);
                    aQ[h][m][3] = *(const unsigned*)(p0 + 8*32 + 8);
                }
        }

        float O[2][2][2][4];
        float ssum[2][2][2];
#pragma unroll
        for (int h = 0; h < 2; h++)
#pragma unroll
            for (int m = 0; m < 2; m++) {
#pragma unroll
                for (int nd = 0; nd < 2; nd++)
#pragma unroll
                    for (int x = 0; x < 4; x++) O[h][m][nd][x] = 0.f;
                ssum[h][m][0] = 0.f; ssum[h][m][1] = 0.f;
            }

        const __nv_bfloat16* kbase = &g_kb[(size_t)b*N_*32];
        const __nv_bfloat16* vbase = &g_vt[(size_t)b*32*N_];

        int k0 = ks*KC_;
#pragma unroll 1
        for (int sl = 0; sl < KC_/16; sl++, k0 += 16) {
            unsigned kb0[2][2], kb1[2][2], vb0[2][2], vb1[2][2];
#pragma unroll
            for (int h = 0; h < 2; h++)
#pragma unroll
                for (int nb = 0; nb < 2; nb++) {
                    const __nv_bfloat16* kp = kbase + (k0 + 8*nb + gq)*32 + 16*h + 2*qu;
                    kb0[h][nb] = *(const unsigned*)(kp);
                    kb1[h][nb] = *(const unsigned*)(kp + 8);
                }
#pragma unroll
            for (int h = 0; h < 2; h++)
#pragma unroll
                for (int nd = 0; nd < 2; nd++) {
                    const __nv_bfloat16* vp = vbase + (size_t)(16*h + 8*nd + gq)*N_ + k0 + 2*qu;
                    vb0[h][nd] = *(const unsigned*)(vp);
                    vb1[h][nd] = *(const unsigned*)(vp + 8);
                }

            float S[2][2][2][4];
#pragma unroll
            for (int h = 0; h < 2; h++)
#pragma unroll
                for (int nb = 0; nb < 2; nb++)
#pragma unroll
                    for (int m = 0; m < 2; m++) {
#pragma unroll
                        for (int x = 0; x < 4; x++) S[h][m][nb][x] = 0.f;
                        mma16816(S[h][m][nb], aQ[h][m], kb0[h][nb], kb1[h][nb]);
                    }

            unsigned aP[2][2][4];
#pragma unroll
            for (int h = 0; h < 2; h++)
#pragma unroll
                for (int m = 0; m < 2; m++)
#pragma unroll
                    for (int nb = 0; nb < 2; nb++) {
                        float e0 = exp2f(S[h][m][nb][0]);
                        float e1 = exp2f(S[h][m][nb][1]);
                        float e2 = exp2f(S[h][m][nb][2]);
                        float e3 = exp2f(S[h][m][nb][3]);
                        ssum[h][m][0] += e0 + e1;
                        ssum[h][m][1] += e2 + e3;
                        aP[h][m][2*nb]   = cvt_bf16x2(e1, e0);
                        aP[h][m][2*nb+1] = cvt_bf16x2(e3, e2);
                    }

#pragma unroll
            for (int h = 0; h < 2; h++)
#pragma unroll
                for (int nd = 0; nd < 2; nd++)
#pragma unroll
                    for (int m = 0; m < 2; m++)
                        mma16816(O[h][m][nd], aP[h][m], vb0[h][nd], vb1[h][nd]);
        }

#pragma unroll
        for (int h = 0; h < 2; h++)
#pragma unroll
            for (int m = 0; m < 2; m++)
#pragma unroll
                for (int x = 0; x < 2; x++) {
                    float v = ssum[h][m][x];
                    v += __shfl_xor_sync(0xffffffffu, v, 1);
                    v += __shfl_xor_sync(0xffffffffu, v, 2);
                    ssum[h][m][x] = v;
                }

        size_t pbase = (size_t)ks*BN_ + (size_t)b*N_;
#pragma unroll
        for (int m = 0; m < 2; m++) {
            int r0 = wq0 + 16*m + gq;
            if (r0 < N_) {
                float* dst = &g_pacc[(pbase + r0)*32];
#pragma unroll
                for (int h = 0; h < 2; h++)
#pragma unroll
                    for (int nd = 0; nd < 2; nd++)
                        *(float2*)&dst[16*h + 8*nd + 2*qu] =
                            make_float2(O[h][m][nd][0], O[h][m][nd][1]);
                if (qu == 0)
                    g_ps[pbase + r0] = make_float2(ssum[0][m][0], ssum[1][m][0]);
            }
            int r1 = r0 + 8;
            if (r1 < N_) {
                float* dst = &g_pacc[(pbase + r1)*32];
#pragma unroll
                for (int h = 0; h < 2; h++)
#pragma unroll
                    for (int nd = 0; nd < 2; nd++)
                        *(float2*)&dst[16*h + 8*nd + 2*qu] =
                            make_float2(O[h][m][nd][2], O[h][m][nd][3]);
                if (qu == 0)
                    g_ps[pbase + r1] = make_float2(ssum[0][m][1], ssum[1][m][1]);
            }
        }
    }
}

// ---------------- fused combine + Wo + LN1 + FFN + LN2 (device body) --------
__device__ __forceinline__ void comb_ff_body(
        const float* swot, const float* sbo, const float* sg1, const float* sb1ln,
        const float* sw1t, const float* sw2, const float* sbf1,
        const float* sbf2, const float* sg2, const float* sbn,
        int r, float hout[32]) {
    u64 accp[16];
    float s0 = 0.f, s1 = 0.f;
#pragma unroll
    for (int u = 0; u < 16; u++) accp[u] = 0ull;
#pragma unroll
    for (int ks = 0; ks < KS_; ks++) {
        const ulonglong2* pa = (const ulonglong2*)&g_pacc[((size_t)ks*BN_ + r)*32];
#pragma unroll
        for (int u = 0; u < 8; u++) {
            ulonglong2 v = pa[u];
            accp[2*u]   = f2add(accp[2*u],   v.x);
            accp[2*u+1] = f2add(accp[2*u+1], v.y);
        }
        float2 s = g_ps[ks*BN_ + r];
        s0 += s.x; s1 += s.y;
    }
    float i0 = 1.f/s0, i1 = 1.f/s1;
    u64 i0p = pack2(i0, i0), i1p = pack2(i1, i1);
    u64 op[16];
#pragma unroll
    for (int u = 0; u < 8; u++) { op[u] = f2mul(accp[u], i0p); op[8+u] = f2mul(accp[8+u], i1p); }

    float hold[32];
    const float4* hr = (const float4*)&g_h[r*32];
#pragma unroll
    for (int u = 0; u < 8; u++) {
        float4 v = hr[u];
        hold[4*u]=v.x; hold[4*u+1]=v.y; hold[4*u+2]=v.z; hold[4*u+3]=v.w;
    }
    float z[32];
#pragma unroll
    for (int j = 0; j < 32; j++) {
        const ulonglong2* wr = (const ulonglong2*)&swot[j*32];
        u64 a0 = 0ull, a1 = 0ull;
#pragma unroll
        for (int u = 0; u < 8; u++) {
            ulonglong2 w = wr[u];
            a0 = f2fma(op[2*u],   w.x, a0);
            a1 = f2fma(op[2*u+1], w.y, a1);
        }
        z[j] = sbo[j] + hold[j] + hadd(f2add(a0, a1));
    }
    float mu = 0.f;
#pragma unroll
    for (int j = 0; j < 32; j++) mu += z[j];
    mu *= (1.f/32.f);
    float var = 0.f;
#pragma unroll
    for (int j = 0; j < 32; j++) { float d = z[j]-mu; var += d*d; }
    var *= (1.f/32.f);
    float inv = rsqrtf(var + 1e-5f);
    float h1[32];
#pragma unroll
    for (int j = 0; j < 32; j++) h1[j] = (z[j]-mu)*inv*sg1[j] + sb1ln[j];

    u64 hp[16], yp[16];
#pragma unroll
    for (int u = 0; u < 16; u++) {
        hp[u] = pack2(h1[2*u], h1[2*u+1]);
        yp[u] = pack2(h1[2*u] + sbf2[2*u], h1[2*u+1] + sbf2[2*u+1]);
    }
#pragma unroll 4
    for (int j = 0; j < 128; j++) {
        const ulonglong2* wr = (const ulonglong2*)&sw1t[j*32];
        u64 a0 = 0ull, a1 = 0ull;
#pragma unroll
        for (int u = 0; u < 8; u++) {
            ulonglong2 w = wr[u];
            a0 = f2fma(hp[2*u],   w.x, a0);
            a1 = f2fma(hp[2*u+1], w.y, a1);
        }
        float uact = fmaxf(sbf1[j] + hadd(f2add(a0, a1)), 0.f);
        u64 up = pack2(uact, uact);
        const ulonglong2* w2r = (const ulonglong2*)&sw2[j*32];
#pragma unroll
        for (int u = 0; u < 8; u++) {
            ulonglong2 w = w2r[u];
            yp[2*u]   = f2fma(up, w.x, yp[2*u]);
            yp[2*u+1] = f2fma(up, w.y, yp[2*u+1]);
        }
    }
    float y[32];
#pragma unroll
    for (int u = 0; u < 16; u++) { float2 v = unpk(yp[u]); y[2*u]=v.x; y[2*u+1]=v.y; }
    float mu2 = 0.f;
#pragma unroll
    for (int j = 0; j < 32; j++) mu2 += y[j];
    mu2 *= (1.f/32.f);
    float var2 = 0.f;
#pragma unroll
    for (int j = 0; j < 32; j++) { float d = y[j]-mu2; var2 += d*d; }
    var2 *= (1.f/32.f);
    float inv2 = rsqrtf(var2 + 1e-5f);
#pragma unroll
    for (int j = 0; j < 32; j++) hout[j] = (y[j]-mu2)*inv2*sg2[j] + sbn[j];
}

// ---- layer-0 epilogue: comb+ff, write h, then emit layer-1 QKV -------------
__global__ void __launch_bounds__(128) k_comb_ff_qkv(
        const float* __restrict__ wo, const float* __restrict__ bo,
        const float* __restrict__ g1, const float* __restrict__ b1,
        const float* __restrict__ w1, const float* __restrict__ bb1,
        const float* __restrict__ w2, const float* __restrict__ bb2,
        const float* __restrict__ g2, const float* __restrict__ b2ln,
        const float* __restrict__ wq, const float* __restrict__ bq) {
    __shared__ float swot[1024], sw1t[4096], sw2[4096];
    __shared__ float sbo[32], sg1[32], sb1ln[32], sbf1[128], sbf2[32], sg2[32], sbn[32];
    __shared__ float sbq[96];
    int t = threadIdx.x;
    for (int i = t; i < 1024; i += 128) {
        int j = i >> 5, ii = i & 31;
        swot[i] = wo[ii*32 + j];
    }
    for (int i = t; i < 4096; i += 128) {
        int j = i >> 5, ii = i & 31;   // sw1t[j*32+ii] = w1[ii*128+j]
        sw1t[i] = w1[ii*128 + j];
        sw2[i]  = w2[i];
    }
    if (t < 32) {
        sbo[t] = bo[t]; sg1[t] = g1[t]; sb1ln[t] = b1[t];
        sbf2[t] = bb2[t]; sg2[t] = g2[t]; sbn[t] = b2ln[t];
    }
    for (int i = t; i < 128; i += 128) sbf1[i] = bb1[i];
    for (int i = t; i < 96; i += 128) sbq[i] = bq[i];
    __syncthreads();

    int r = blockIdx.x*128 + t;
    int b = r / N_, n = r % N_;
    float hnew[32];
    comb_ff_body(swot, sbo, sg1, sb1ln, sw1t, sw2, sbf1, sbf2, sg2, sbn, r, hnew);
    float4* hw = (float4*)&g_h[r*32];
#pragma unroll
    for (int u = 0; u < 8; u++)
        hw[u] = make_float4(hnew[4*u], hnew[4*u+1], hnew[4*u+2], hnew[4*u+3]);

    // reuse sw1t region for the layer-1 QKV weights (96x32 = 3072 floats)
    __syncthreads();
    for (int i = t; i < 96*32; i += 128) {
        int j = i >> 5, ii = i & 31;
        sw1t[i] = wq[ii*96 + j];
    }
    __syncthreads();
    qkv_emit(hnew, sw1t, sbq, r, b, n);
}

__global__ void __launch_bounds__(128) k_comb_ff_out(
        const float* __restrict__ wo, const float* __restrict__ bo,
        const float* __restrict__ g1, const float* __restrict__ b1,
        const float* __restrict__ w1, const float* __restrict__ bb1,
        const float* __restrict__ w2, const float* __restrict__ bb2,
        const float* __restrict__ g2, const float* __restrict__ b2ln,
        const float* __restrict__ wout, const float* __restrict__ bout,
        float* __restrict__ out) {
    __shared__ float swot[1024], sw1t[4096], sw2[4096];
    __shared__ float sbo[32], sg1[32], sb1ln[32], sbf1[128], sbf2[32], sg2[32], sbn[32];
    __shared__ float swo2[32];
    __shared__ float sb0;
    int t = threadIdx.x;
    for (int i = t; i < 1024; i += 128) {
        int j = i >> 5, ii = i & 31;
        swot[i] = wo[ii*32 + j];
    }
    for (int i = t; i < 4096; i += 128) {
        int j = i >> 5, ii = i & 31;
        sw1t[i] = w1[ii*128 + j];
        sw2[i]  = w2[i];
    }
    if (t < 32) {
        sbo[t] = bo[t]; sg1[t] = g1[t]; sb1ln[t] = b1[t];
        sbf2[t] = bb2[t]; sg2[t] = g2[t]; sbn[t] = b2ln[t];
        swo2[t] = wout[t];
    }
    if (t == 0) sb0 = bout[0];
    for (int i = t; i < 128; i += 128) sbf1[i] = bb1[i];
    __syncthreads();

    int r = blockIdx.x*128 + t;
    float hnew[32];
    comb_ff_body(swot, sbo, sg1, sb1ln, sw1t, sw2, sbf1, sbf2, sg2, sbn, r, hnew);
    float a = sb0;
#pragma unroll
    for (int j = 0; j < 32; j++) a += hnew[j]*swo2[j];
    out[r] = a;
}

// ---------------- launch -----------------------------------------------------
extern "C" void kernel_launch(void* const* d_in, const int* in_sizes, int n_in,
                              void* d_out, int out_size) {
    const float* pm    = (const float*)d_in[0];
    const float* ft    = (const float*)d_in[1];
    const int*   ei    = (const int*)  d_in[2];
    const float* wch0  = (const float*)d_in[3];
    const float* wch1  = (const float*)d_in[4];
    const float* bch   = (const float*)d_in[5];
    const float* win   = (const float*)d_in[6];
    const float* bin   = (const float*)d_in[7];
    const float* wqkv  = (const float*)d_in[8];
    const float* bqkv  = (const float*)d_in[9];
    const float* wo    = (const float*)d_in[10];
    const float* bo    = (const float*)d_in[11];
    const float* ln1g  = (const float*)d_in[12];
    const float* ln1b  = (const float*)d_in[13];
    const float* wff1  = (const float*)d_in[14];
    const float* bff1  = (const float*)d_in[15];
    const float* wff2  = (const float*)d_in[16];
    const float* bff2  = (const float*)d_in[17];
    const float* ln2g  = (const float*)d_in[18];
    const float* ln2b  = (const float*)d_in[19];
    const float* wout  = (const float*)d_in[20];
    const float* bout  = (const float*)d_in[21];
    float* out = (float*)d_out;

    k_pre <<<230, 256>>>(pm, ft);
    k_deg <<<(E_+255)/256, 256>>>(ei);
    k_scan<<<1, 256>>>();
    k_fill<<<(E_+255)/256, 256>>>(ei);
    k_gcn_qkv<<<BN_/128, 128>>>(wch0, wch1, bch, win, bin, wqkv, bqkv);

    k_attn_tc<<<AGRID_, 128>>>();
    k_comb_ff_qkv<<<BN_/128, 128>>>(wo, bo, ln1g, ln1b,
                                    wff1, bff1, wff2, bff2, ln2g, ln2b,
                                    wqkv + 32*96, bqkv + 96);
    k_attn_tc<<<AGRID_, 128>>>();
    k_comb_ff_out<<<BN_/128, 128>>>(wo + 1024, bo + 32, ln1g + 32, ln1b + 32,
                                    wff1 + 32*128, bff1 + 128,
                                    wff2 + 128*32, bff2 + 32,
                                    ln2g + 32, ln2b + 32,
                                    wout, bout, out);
}